// round 2
// baseline (speedup 1.0000x reference)
#include <cuda_runtime.h>
#include <cstdint>

// Segment mean readout:
//   in0: atom_hiddens  float32 [N_ATOMS, 300]
//   in1: a_scope       int32   [N_GRAPHS, 2]  (start, size) -- harness converts
//                                             the reference's int64 to int32
//   out: mol_vecs      float32 [N_GRAPHS, 300]
//
// D = 300 floats = 75 float4 per row (row stride 1200 B, 16B-aligned).
// One thread per (graph, float4-chunk): warp reads contiguous 512B, input is
// streamed exactly once -> HBM-bound at the roofline.

#define D4 75  // 300 / 4

__global__ void readout_mean_kernel(const float4* __restrict__ x,
                                    const int* __restrict__ scope,
                                    float4* __restrict__ out,
                                    int n_graphs) {
    int idx = blockIdx.x * blockDim.x + threadIdx.x;
    int total = n_graphs * D4;
    if (idx >= total) return;

    int g = idx / D4;
    int d = idx - g * D4;

    int start = __ldg(&scope[2 * g]);
    int size  = __ldg(&scope[2 * g + 1]);

    float4 acc = make_float4(0.f, 0.f, 0.f, 0.f);
    const float4* p = x + (long long)start * D4 + d;
    #pragma unroll 4
    for (int a = 0; a < size; ++a) {
        float4 v = __ldg(p);
        acc.x += v.x; acc.y += v.y; acc.z += v.z; acc.w += v.w;
        p += D4;
    }

    float inv = (size > 0) ? (1.0f / (float)size) : 0.0f;
    acc.x *= inv; acc.y *= inv; acc.z *= inv; acc.w *= inv;
    out[(long long)g * D4 + d] = acc;
}

extern "C" void kernel_launch(void* const* d_in, const int* in_sizes, int n_in,
                              void* d_out, int out_size) {
    const float4* x = (const float4*)d_in[0];
    const int* scope = (const int*)d_in[1];
    float4* out = (float4*)d_out;

    int n_graphs = in_sizes[1] / 2;  // a_scope has 2 ints per graph
    int total = n_graphs * D4;
    int threads = 256;
    int blocks = (total + threads - 1) / threads;
    readout_mean_kernel<<<blocks, threads>>>(x, scope, out, n_graphs);
}

// round 3
// speedup vs baseline: 1.0053x; 1.0053x over previous
#include <cuda_runtime.h>
#include <cstdint>

// Segment mean readout:
//   in0: atom_hiddens  float32 [N_ATOMS, 300]
//   in1: a_scope       int32   [N_GRAPHS, 2]  (start, size), contiguous segments
//   out: mol_vecs      float32 [N_GRAPHS, 300]
//
// HBM-bound: 1.2 GB read + 60 MB write, ~157us floor at 8 TB/s.
// One thread per (graph, float4-lane). Hot path: size==20 (uniform dataset)
// fully unrolled -> 20 independent streaming loads batched (high MLP).

#define D4 75  // 300 / 4

__global__ void readout_mean_kernel(const float4* __restrict__ x,
                                    const int* __restrict__ scope,
                                    float4* __restrict__ out,
                                    int n_graphs) {
    int idx = blockIdx.x * blockDim.x + threadIdx.x;
    int total = n_graphs * D4;
    if (idx >= total) return;

    int g = idx / D4;
    int d = idx - g * D4;

    int start = __ldg(&scope[2 * g]);
    int size  = __ldg(&scope[2 * g + 1]);

    const float4* p = x + (long long)start * D4 + d;

    float4 acc0 = make_float4(0.f, 0.f, 0.f, 0.f);
    float4 acc1 = make_float4(0.f, 0.f, 0.f, 0.f);

    if (size == 20) {
        // Fully unrolled: 20 independent streaming loads, two accumulator
        // chains for ILP. Compiler front-batches the LDGs -> MLP ~20.
        #pragma unroll
        for (int a = 0; a < 20; a += 2) {
            float4 v0 = __ldcs(p + (a + 0) * D4);
            float4 v1 = __ldcs(p + (a + 1) * D4);
            acc0.x += v0.x; acc0.y += v0.y; acc0.z += v0.z; acc0.w += v0.w;
            acc1.x += v1.x; acc1.y += v1.y; acc1.z += v1.z; acc1.w += v1.w;
        }
    } else {
        int a = 0;
        for (; a + 2 <= size; a += 2) {
            float4 v0 = __ldcs(p + (a + 0) * D4);
            float4 v1 = __ldcs(p + (a + 1) * D4);
            acc0.x += v0.x; acc0.y += v0.y; acc0.z += v0.z; acc0.w += v0.w;
            acc1.x += v1.x; acc1.y += v1.y; acc1.z += v1.z; acc1.w += v1.w;
        }
        if (a < size) {
            float4 v = __ldcs(p + a * D4);
            acc0.x += v.x; acc0.y += v.y; acc0.z += v.z; acc0.w += v.w;
        }
    }

    float inv = (size > 0) ? (1.0f / (float)size) : 0.0f;
    float4 r;
    r.x = (acc0.x + acc1.x) * inv;
    r.y = (acc0.y + acc1.y) * inv;
    r.z = (acc0.z + acc1.z) * inv;
    r.w = (acc0.w + acc1.w) * inv;
    __stcs(&out[(long long)g * D4 + d], r);
}

extern "C" void kernel_launch(void* const* d_in, const int* in_sizes, int n_in,
                              void* d_out, int out_size) {
    const float4* x = (const float4*)d_in[0];
    const int* scope = (const int*)d_in[1];
    float4* out = (float4*)d_out;

    int n_graphs = in_sizes[1] / 2;
    int total = n_graphs * D4;
    int threads = 256;
    int blocks = (total + threads - 1) / threads;
    readout_mean_kernel<<<blocks, threads>>>(x, scope, out, n_graphs);
}